// round 1
// baseline (speedup 1.0000x reference)
#include <cuda_runtime.h>

// ProjectionLoss: fused GT-projection + pred-projection + smooth-MSE + mean.
// Inputs (metadata order):
//   d_in[0] kps_world_gt   [B,J,3]   f32
//   d_in[1] kps_world_pred [B,J,3]   f32
//   d_in[2] gt_R           [B,V,3,3] f32
//   d_in[3] gt_t           [B,V,3]   f32
//   d_in[4] K              [V,3,3]   f32
//   d_in[5] cam_preds      [B,V,3,4] f32
// Output: scalar f32 = mean_b( sum_{v,j,2}(smooth(diff)) / 2 )

#define B_TOTAL 16384
#define V_NUM   8
#define J_NUM   64
#define NB      8                      // batch elements per block
#define THREADS (NB * J_NUM)           // 512
#define NBLOCKS (B_TOTAL / NB)         // 2048

#define THRESH    400.0f
#define POW_CONST 219.7120972f         // 400^0.9 (double-precision, rounded to f32)

__device__ float g_partials[NBLOCKS];

__global__ __launch_bounds__(THREADS)
void proj_loss_main(const float* __restrict__ gt_kps,
                    const float* __restrict__ pr_kps,
                    const float* __restrict__ gt_R,
                    const float* __restrict__ gt_t,
                    const float* __restrict__ Kmat,
                    const float* __restrict__ cam)
{
    __shared__ __align__(16) float sGT[NB * J_NUM * 3];   // 1536
    __shared__ __align__(16) float sPR[NB * J_NUM * 3];   // 1536
    __shared__ __align__(16) float sR [NB * V_NUM * 9];   // 576
    __shared__ __align__(16) float sT [NB * V_NUM * 3];   // 192
    __shared__ __align__(16) float sC [NB * V_NUM * 12];  // 768
    __shared__ float sK[V_NUM * 9];                        // 72
    __shared__ float sWarp[THREADS / 32];

    const int tid = threadIdx.x;
    const long b0 = (long)blockIdx.x * NB;

    // ---- cooperative staged loads (all float4-aligned regions) ----
    {
        const float4* g = (const float4*)(gt_kps + b0 * (J_NUM * 3));
        float4* s = (float4*)sGT;
        for (int i = tid; i < NB * J_NUM * 3 / 4; i += THREADS) s[i] = g[i];
    }
    {
        const float4* g = (const float4*)(pr_kps + b0 * (J_NUM * 3));
        float4* s = (float4*)sPR;
        for (int i = tid; i < NB * J_NUM * 3 / 4; i += THREADS) s[i] = g[i];
    }
    {
        const float4* g = (const float4*)(gt_R + b0 * (V_NUM * 9));
        float4* s = (float4*)sR;
        for (int i = tid; i < NB * V_NUM * 9 / 4; i += THREADS) s[i] = g[i];
    }
    {
        const float4* g = (const float4*)(gt_t + b0 * (V_NUM * 3));
        float4* s = (float4*)sT;
        for (int i = tid; i < NB * V_NUM * 3 / 4; i += THREADS) s[i] = g[i];
    }
    {
        const float4* g = (const float4*)(cam + b0 * (V_NUM * 12));
        float4* s = (float4*)sC;
        for (int i = tid; i < NB * V_NUM * 12 / 4; i += THREADS) s[i] = g[i];
    }
    if (tid < V_NUM * 9) sK[tid] = Kmat[tid];
    __syncthreads();

    // ---- compute: one thread = one (b_local, j), loop over 8 views ----
    const int bl = tid >> 6;       // 0..7
    const int j  = tid & 63;       // 0..63

    const float X0 = sGT[bl * 192 + j * 3 + 0];
    const float X1 = sGT[bl * 192 + j * 3 + 1];
    const float X2 = sGT[bl * 192 + j * 3 + 2];
    const float P0 = sPR[bl * 192 + j * 3 + 0];
    const float P1 = sPR[bl * 192 + j * 3 + 1];
    const float P2 = sPR[bl * 192 + j * 3 + 2];

    float acc = 0.0f;

    #pragma unroll
    for (int v = 0; v < V_NUM; v++) {
        const float* R = &sR[bl * 72 + v * 9];
        const float* t = &sT[bl * 24 + v * 3];
        const float* c = &sC[bl * 96 + v * 12];
        const float* k = &sK[v * 9];

        // GT: Xc = R @ X + t
        float xc = fmaf(R[0], X0, fmaf(R[1], X1, fmaf(R[2], X2, t[0])));
        float yc = fmaf(R[3], X0, fmaf(R[4], X1, fmaf(R[5], X2, t[1])));
        float zc = fmaf(R[6], X0, fmaf(R[7], X1, fmaf(R[8], X2, t[2])));
        // x = K @ Xc
        float u  = fmaf(k[0], xc, fmaf(k[1], yc, k[2] * zc));
        float vv = fmaf(k[3], xc, fmaf(k[4], yc, k[5] * zc));
        float w  = fmaf(k[6], xc, fmaf(k[7], yc, k[8] * zc));
        float iw = 1.0f / w;
        float gx = u * iw;
        float gy = vv * iw;

        // pred: Xcp = cam @ [P;1]
        float xp = fmaf(c[0], P0, fmaf(c[1], P1, fmaf(c[2],  P2, c[3])));
        float yp = fmaf(c[4], P0, fmaf(c[5], P1, fmaf(c[6],  P2, c[7])));
        float zp = fmaf(c[8], P0, fmaf(c[9], P1, fmaf(c[10], P2, c[11])));
        float up  = fmaf(k[0], xp, fmaf(k[1], yp, k[2] * zp));
        float vp  = fmaf(k[3], xp, fmaf(k[4], yp, k[5] * zp));
        float wp  = fmaf(k[6], xp, fmaf(k[7], yp, k[8] * zp));
        float iwp = 1.0f / wp;
        float px = up * iwp;
        float py = vp * iwp;

        float dx = gx - px;
        float dy = gy - py;
        float d2x = dx * dx;
        float d2y = dy * dy;

        acc += (d2x > THRESH) ? __powf(d2x, 0.1f) * POW_CONST : d2x;
        acc += (d2y > THRESH) ? __powf(d2y, 0.1f) * POW_CONST : d2y;
    }

    // ---- block reduction (warp shuffle tree + one partial per block) ----
    #pragma unroll
    for (int o = 16; o > 0; o >>= 1)
        acc += __shfl_xor_sync(0xFFFFFFFFu, acc, o);

    const int lane = tid & 31;
    const int wid  = tid >> 5;
    if (lane == 0) sWarp[wid] = acc;
    __syncthreads();

    if (wid == 0) {
        float s = (lane < THREADS / 32) ? sWarp[lane] : 0.0f;
        #pragma unroll
        for (int o = 8; o > 0; o >>= 1)
            s += __shfl_xor_sync(0xFFFFFFFFu, s, o);
        if (lane == 0) g_partials[blockIdx.x] = s;
    }
}

__global__ __launch_bounds__(1024)
void proj_loss_finish(float* __restrict__ out)
{
    __shared__ float sWarp[32];
    const int tid = threadIdx.x;

    float s = g_partials[tid] + g_partials[tid + 1024];

    #pragma unroll
    for (int o = 16; o > 0; o >>= 1)
        s += __shfl_xor_sync(0xFFFFFFFFu, s, o);

    const int lane = tid & 31;
    const int wid  = tid >> 5;
    if (lane == 0) sWarp[wid] = s;
    __syncthreads();

    if (wid == 0) {
        float t = (lane < 32) ? sWarp[lane] : 0.0f;
        #pragma unroll
        for (int o = 16; o > 0; o >>= 1)
            t += __shfl_xor_sync(0xFFFFFFFFu, t, o);
        if (lane == 0)
            out[0] = t * (1.0f / (2.0f * (float)B_TOTAL));
    }
}

extern "C" void kernel_launch(void* const* d_in, const int* in_sizes, int n_in,
                              void* d_out, int out_size)
{
    const float* gt_kps = (const float*)d_in[0];
    const float* pr_kps = (const float*)d_in[1];
    const float* gt_R   = (const float*)d_in[2];
    const float* gt_t   = (const float*)d_in[3];
    const float* Kmat   = (const float*)d_in[4];
    const float* cam    = (const float*)d_in[5];
    float* out = (float*)d_out;

    proj_loss_main<<<NBLOCKS, THREADS>>>(gt_kps, pr_kps, gt_R, gt_t, Kmat, cam);
    proj_loss_finish<<<1, 1024>>>(out);
}

// round 2
// speedup vs baseline: 1.0589x; 1.0589x over previous
#include <cuda_runtime.h>

// ProjectionLoss fused single-kernel:
//   prepass: fold K into gt [R|t] and cam_preds -> two 3x4 matrices per (b,v),
//            stored packed for f32x2 math (rows 0/1 interleaved per column + w-row)
//   main:    per (b,j) thread, 8 views, packed fma.rn.f32x2 matvecs,
//            single rcp per view via combined fraction, smooth-MSE accumulate
//   tail:    last block reduces per-block partials (deterministic order)

#define B_TOTAL 16384
#define V_NUM   8
#define J_NUM   64
#define NB      8
#define THREADS (NB * J_NUM)          // 512
#define NBLOCKS (B_TOTAL / NB)        // 2048

#define THRESH    400.0f
#define POW_CONST 219.7120972f        // 400^0.9

__device__ float g_partials[NBLOCKS];
__device__ int   g_count = 0;

// ---- f32x2 packed helpers (sm_103a) ----
__device__ __forceinline__ unsigned long long pk2(float lo, float hi) {
    unsigned long long r;
    asm("mov.b64 %0, {%1, %2};" : "=l"(r) : "f"(lo), "f"(hi));
    return r;
}
__device__ __forceinline__ void upk2(float& lo, float& hi, unsigned long long v) {
    asm("mov.b64 {%0, %1}, %2;" : "=f"(lo), "=f"(hi) : "l"(v));
}
__device__ __forceinline__ unsigned long long fma2(unsigned long long a,
                                                   unsigned long long b,
                                                   unsigned long long c) {
    unsigned long long d;
    asm("fma.rn.f32x2 %0, %1, %2, %3;" : "=l"(d) : "l"(a), "l"(b), "l"(c));
    return d;
}
__device__ __forceinline__ unsigned long long mul2(unsigned long long a,
                                                   unsigned long long b) {
    unsigned long long d;
    asm("mul.rn.f32x2 %0, %1, %2;" : "=l"(d) : "l"(a), "l"(b));
    return d;
}
__device__ __forceinline__ float rcpa(float x) {
    float r;
    asm("rcp.approx.f32 %0, %1;" : "=f"(r) : "f"(x));
    return r;
}

__global__ __launch_bounds__(THREADS)
void proj_loss_fused(const float* __restrict__ gt_kps,
                     const float* __restrict__ pr_kps,
                     const float* __restrict__ gt_R,
                     const float* __restrict__ gt_t,
                     const float* __restrict__ Kmat,
                     const float* __restrict__ cam,
                     float* __restrict__ out)
{
    // staging
    __shared__ __align__(16) float sGT[NB * J_NUM * 3];   // 1536
    __shared__ __align__(16) float sPR[NB * J_NUM * 3];   // 1536
    __shared__ __align__(16) float sR [NB * V_NUM * 9];   // 576
    __shared__ __align__(16) float sT [NB * V_NUM * 3];   // 192
    __shared__ __align__(16) float sC [NB * V_NUM * 12];  // 768
    __shared__ float sK[V_NUM * 9];                       // 72
    // folded matrices, packed layout:
    //  per proj p (= (bl*8+v)*2+which): 8 floats [c0x,c0y, c1x,c1y, c2x,c2y, c3x,c3y]
    __shared__ __align__(16) float sUVf[NB * V_NUM * 2 * 8];  // 1024
    __shared__ __align__(16) float sWf [NB * V_NUM * 2 * 4];  // 512
    __shared__ float sWarp[THREADS / 32];
    __shared__ int   sIsLast;

    const int tid = threadIdx.x;
    const long b0 = (long)blockIdx.x * NB;

    // ---- cooperative float4 staged loads ----
    {
        const float4* g = (const float4*)(gt_kps + b0 * (J_NUM * 3));
        float4* s = (float4*)sGT;
        for (int i = tid; i < NB * J_NUM * 3 / 4; i += THREADS) s[i] = g[i];
    }
    {
        const float4* g = (const float4*)(pr_kps + b0 * (J_NUM * 3));
        float4* s = (float4*)sPR;
        for (int i = tid; i < NB * J_NUM * 3 / 4; i += THREADS) s[i] = g[i];
    }
    {
        const float4* g = (const float4*)(gt_R + b0 * (V_NUM * 9));
        float4* s = (float4*)sR;
        for (int i = tid; i < NB * V_NUM * 9 / 4; i += THREADS) s[i] = g[i];
    }
    {
        const float4* g = (const float4*)(gt_t + b0 * (V_NUM * 3));
        float4* s = (float4*)sT;
        for (int i = tid; i < NB * V_NUM * 3 / 4; i += THREADS) s[i] = g[i];
    }
    {
        const float4* g = (const float4*)(cam + b0 * (V_NUM * 12));
        float4* s = (float4*)sC;
        for (int i = tid; i < NB * V_NUM * 12 / 4; i += THREADS) s[i] = g[i];
    }
    if (tid < V_NUM * 9) sK[tid] = Kmat[tid];
    __syncthreads();

    // ---- prepass: fold K into [R|t] (gt) and cam (pred) ----
    // 1536 output elements; 3 per thread.
    #pragma unroll
    for (int rep = 0; rep < 3; rep++) {
        int idx = tid + rep * THREADS;          // 0..1535
        int p   = idx / 12;                      // 0..127
        int el  = idx % 12;
        int bl    = p >> 4;
        int v     = (p >> 1) & 7;
        int which = p & 1;                       // 0=gt, 1=pred
        int comp, c;
        if (el < 8) { c = el >> 1; comp = el & 1; }
        else        { c = el - 8;  comp = 2;     }
        const float* krow = &sK[v * 9 + comp * 3];
        float val;
        if (which == 0) {
            if (c < 3) {
                const float* R = &sR[bl * 72 + v * 9];
                val = fmaf(krow[0], R[0 * 3 + c],
                      fmaf(krow[1], R[1 * 3 + c],
                           krow[2] * R[2 * 3 + c]));
            } else {
                const float* t = &sT[bl * 24 + v * 3];
                val = fmaf(krow[0], t[0], fmaf(krow[1], t[1], krow[2] * t[2]));
            }
        } else {
            const float* cm = &sC[bl * 96 + v * 12];
            val = fmaf(krow[0], cm[0 * 4 + c],
                  fmaf(krow[1], cm[1 * 4 + c],
                       krow[2] * cm[2 * 4 + c]));
        }
        if (el < 8) sUVf[p * 8 + c * 2 + comp] = val;
        else        sWf [p * 4 + c]            = val;
    }
    __syncthreads();

    // ---- main compute: one thread = (b_local, j), loop 8 views ----
    const int bl = tid >> 6;
    const int j  = tid & 63;

    const float X0 = sGT[bl * 192 + j * 3 + 0];
    const float X1 = sGT[bl * 192 + j * 3 + 1];
    const float X2 = sGT[bl * 192 + j * 3 + 2];
    const float P0 = sPR[bl * 192 + j * 3 + 0];
    const float P1 = sPR[bl * 192 + j * 3 + 1];
    const float P2 = sPR[bl * 192 + j * 3 + 2];

    const unsigned long long X0b = pk2(X0, X0), X1b = pk2(X1, X1), X2b = pk2(X2, X2);
    const unsigned long long P0b = pk2(P0, P0), P1b = pk2(P1, P1), P2b = pk2(P2, P2);

    const ulonglong2* sUV2 = (const ulonglong2*)sUVf;
    const float4*     sW4  = (const float4*)sWf;

    float acc = 0.0f;

    #pragma unroll
    for (int v = 0; v < V_NUM; v++) {
        const int pg = (bl * 8 + v) * 2;        // gt proj index
        const int pp = pg + 1;                  // pred proj index

        // gt: uv = pairs . [X;1], w = wrow . [X;1]
        ulonglong2 ga = sUV2[pg * 2], gb = sUV2[pg * 2 + 1];
        unsigned long long uv = gb.y;
        uv = fma2(gb.x, X2b, uv);
        uv = fma2(ga.y, X1b, uv);
        uv = fma2(ga.x, X0b, uv);
        float4 gw = sW4[pg];
        float w = fmaf(gw.x, X0, fmaf(gw.y, X1, fmaf(gw.z, X2, gw.w)));

        // pred
        ulonglong2 pa = sUV2[pp * 2], pb = sUV2[pp * 2 + 1];
        unsigned long long upv = pb.y;
        upv = fma2(pb.x, P2b, upv);
        upv = fma2(pa.y, P1b, upv);
        upv = fma2(pa.x, P0b, upv);
        float4 pw = sW4[pp];
        float wp = fmaf(pw.x, P0, fmaf(pw.y, P1, fmaf(pw.z, P2, pw.w)));

        // dx = u/w - up/wp = (u*wp - up*w) * rcp(w*wp)  -> one MUFU per view
        float r = rcpa(w * wp);
        unsigned long long num = mul2(uv, pk2(wp, wp));
        num = fma2(upv, pk2(-w, -w), num);
        unsigned long long d  = mul2(num, pk2(r, r));
        unsigned long long d2 = mul2(d, d);
        float d2x, d2y;
        upk2(d2x, d2y, d2);

        acc += (d2x > THRESH) ? __powf(d2x, 0.1f) * POW_CONST : d2x;
        acc += (d2y > THRESH) ? __powf(d2y, 0.1f) * POW_CONST : d2y;
    }

    // ---- block reduction ----
    #pragma unroll
    for (int o = 16; o > 0; o >>= 1)
        acc += __shfl_xor_sync(0xFFFFFFFFu, acc, o);

    const int lane = tid & 31;
    const int wid  = tid >> 5;
    if (lane == 0) sWarp[wid] = acc;
    __syncthreads();

    if (wid == 0) {
        float s = (lane < THREADS / 32) ? sWarp[lane] : 0.0f;
        #pragma unroll
        for (int o = 8; o > 0; o >>= 1)
            s += __shfl_xor_sync(0xFFFFFFFFu, s, o);
        if (lane == 0) g_partials[blockIdx.x] = s;
    }

    // ---- fused finish: last-arriving block reduces all partials ----
    __threadfence();
    if (tid == 0) {
        int c = atomicAdd(&g_count, 1);
        sIsLast = (c == NBLOCKS - 1);
    }
    __syncthreads();

    if (sIsLast) {
        float s = 0.0f;
        #pragma unroll
        for (int rep = 0; rep < NBLOCKS / THREADS; rep++)
            s += g_partials[tid + rep * THREADS];

        #pragma unroll
        for (int o = 16; o > 0; o >>= 1)
            s += __shfl_xor_sync(0xFFFFFFFFu, s, o);
        if (lane == 0) sWarp[wid] = s;
        __syncthreads();

        if (wid == 0) {
            float t = (lane < THREADS / 32) ? sWarp[lane] : 0.0f;
            #pragma unroll
            for (int o = 8; o > 0; o >>= 1)
                t += __shfl_xor_sync(0xFFFFFFFFu, t, o);
            if (lane == 0) {
                out[0] = t * (1.0f / (2.0f * (float)B_TOTAL));
                g_count = 0;   // reset for next graph replay
            }
        }
    }
}

extern "C" void kernel_launch(void* const* d_in, const int* in_sizes, int n_in,
                              void* d_out, int out_size)
{
    const float* gt_kps = (const float*)d_in[0];
    const float* pr_kps = (const float*)d_in[1];
    const float* gt_R   = (const float*)d_in[2];
    const float* gt_t   = (const float*)d_in[3];
    const float* Kmat   = (const float*)d_in[4];
    const float* cam    = (const float*)d_in[5];
    float* out = (float*)d_out;

    proj_loss_fused<<<NBLOCKS, THREADS>>>(gt_kps, pr_kps, gt_R, gt_t, Kmat, cam, out);
}